// round 9
// baseline (speedup 1.0000x reference)
#include <cuda_runtime.h>
#include <cuda_bf16.h>
#include <cstdint>

#define N_NODES 50000
#define N_EDGES 800000
#define N_GRAPHS 256
#define DD 128
#define DV 32
#define NLAYERS 3
#define TILE_M 128
#define NTILES ((N_NODES + TILE_M - 1) / TILE_M)
#define BN_EPS 1e-5f
#define GRID_GEMM 148

// ---- k_gemm smem layout (bytes) ----
#define OFF_W1   0
#define OFF_W2   65536
#define WLO_OFF  32768
#define OFF_A    131072          // 8 warps x 8KB (hi at +0, lo at +4096)
#define OFF_B1   196608
#define OFF_B2   197120
#define SMEM_KM  197632

__device__ __forceinline__ uint32_t smem_u32(const void* p) {
    uint32_t a;
    asm("{ .reg .u64 t; cvta.to.shared.u64 t, %1; cvt.u32.u64 %0, t; }" : "=r"(a) : "l"(p));
    return a;
}
__device__ __forceinline__ uint32_t pack_bf16x2(float a, float b) {
    uint32_t r;
    asm("cvt.rn.bf16x2.f32 %0, %1, %2;" : "=r"(r) : "f"(b), "f"(a));
    return r;
}
__device__ __forceinline__ float bf_round(float v) {
    return __bfloat162float(__float2bfloat16(v));
}
__device__ __forceinline__ void ldsm_x4(uint32_t* r, uint32_t addr) {
    asm volatile("ldmatrix.sync.aligned.m8n8.x4.shared.b16 {%0,%1,%2,%3}, [%4];"
                 : "=r"(r[0]), "=r"(r[1]), "=r"(r[2]), "=r"(r[3]) : "r"(addr));
}
__device__ __forceinline__ void ldsm_x4_t(uint32_t* r, uint32_t addr) {
    asm volatile("ldmatrix.sync.aligned.m8n8.x4.trans.shared.b16 {%0,%1,%2,%3}, [%4];"
                 : "=r"(r[0]), "=r"(r[1]), "=r"(r[2]), "=r"(r[3]) : "r"(addr));
}
__device__ __forceinline__ void mma16816(float* c, const uint32_t* a, uint32_t b0, uint32_t b1) {
    asm volatile(
        "mma.sync.aligned.m16n8k16.row.col.f32.bf16.bf16.f32 "
        "{%0,%1,%2,%3}, {%4,%5,%6,%7}, {%8,%9}, {%0,%1,%2,%3};"
        : "+f"(c[0]), "+f"(c[1]), "+f"(c[2]), "+f"(c[3])
        : "r"(a[0]), "r"(a[1]), "r"(a[2]), "r"(a[3]), "r"(b0), "r"(b1));
}

__device__ __forceinline__ void gemm_chain(float (*acc)[4], uint32_t aBase, uint32_t bBase,
                                           int selk, int nsel, int kofs, int l7) {
    #pragma unroll 1
    for (int ks = 0; ks < 8; ks++) {
        uint32_t ah[4], al[4];
        uint32_t aaddr = aBase + (uint32_t)(((2 * ks + selk) ^ l7) << 4);
        ldsm_x4(ah, aaddr);
        ldsm_x4(al, aaddr + 4096);
        uint32_t bRow = bBase + (uint32_t)(16 * ks + kofs) * 256;
        #pragma unroll
        for (int jp = 0; jp < 8; jp++) {
            uint32_t bh[4], bl[4];
            uint32_t baddr = bRow + (uint32_t)(((2 * jp + nsel) ^ l7) << 4);
            ldsm_x4_t(bh, baddr);
            ldsm_x4_t(bl, baddr + WLO_OFF);
            mma16816(acc[2*jp],   ah, bh[0], bh[1]);
            mma16816(acc[2*jp+1], ah, bh[2], bh[3]);
            mma16816(acc[2*jp],   al, bh[0], bh[1]);
            mma16816(acc[2*jp+1], al, bh[2], bh[3]);
            mma16816(acc[2*jp],   ah, bl[0], bl[1]);
            mma16816(acc[2*jp+1], ah, bl[2], bl[3]);
        }
    }
}

// ---------------- scratch ----------------
__device__ float4 g_xa[N_NODES * DV];
__device__ float4 g_xb[N_NODES * DV];
__device__ uint2  g_hhi[N_NODES * 32];
__device__ uint2  g_hlo[N_NODES * 32];
__device__ int    g_deg[N_NODES];
__device__ int    g_off[N_NODES + 1];
__device__ int    g_cur[N_NODES];
__device__ int    g_csr[N_EDGES];
__device__ float  g_stats[NLAYERS * 2 * DD];
__device__ float4 g_pool[N_GRAPHS * DV];
__device__ float  g_cnt[N_GRAPHS];

// ---------------- CSR build ----------------
__global__ void k_deg(const int* __restrict__ ei) {
    int e = blockIdx.x * blockDim.x + threadIdx.x;
    if (e >= N_EDGES) return;
    unsigned d = (unsigned)ei[N_EDGES + e];
    if (d < N_NODES) atomicAdd(&g_deg[d], 1);
}
__global__ void k_scan() {
    __shared__ int sbuf[1024];
    __shared__ int carry;
    if (threadIdx.x == 0) carry = 0;
    __syncthreads();
    for (int base = 0; base < N_NODES; base += 1024) {
        int i = base + threadIdx.x;
        int v = (i < N_NODES) ? g_deg[i] : 0;
        sbuf[threadIdx.x] = v;
        __syncthreads();
        for (int ofs = 1; ofs < 1024; ofs <<= 1) {
            int tv = (threadIdx.x >= ofs) ? sbuf[threadIdx.x - ofs] : 0;
            __syncthreads();
            sbuf[threadIdx.x] += tv;
            __syncthreads();
        }
        if (i < N_NODES) g_off[i + 1] = carry + sbuf[threadIdx.x];
        __syncthreads();
        if (threadIdx.x == 0) carry += sbuf[1023];
        __syncthreads();
    }
    if (threadIdx.x == 0) g_off[0] = 0;
}
__global__ void k_fill(const int* __restrict__ ei) {
    int e = blockIdx.x * blockDim.x + threadIdx.x;
    if (e >= N_EDGES) return;
    unsigned s = (unsigned)ei[e];
    unsigned d = (unsigned)ei[N_EDGES + e];
    if (s >= N_NODES || d >= N_NODES) return;
    int pos = atomicAdd(&g_cur[d], 1);
    g_csr[g_off[d] + pos] = (int)s;
}

// ---------------- gather: CSR walk + GIN combine + BN fold -> H hi/lo ----------------
__global__ void __launch_bounds__(256) k_gather(
    const float4* __restrict__ in,
    const float* __restrict__ stats_in,
    const float* __restrict__ gm, const float* __restrict__ bt,
    const float* __restrict__ epsp)
{
    const int lane = threadIdx.x & 31;
    const int gwarp = (blockIdx.x * blockDim.x + threadIdx.x) >> 5;
    const int nwarps = (gridDim.x * blockDim.x) >> 5;
    const float eps1 = 1.0f + epsp[0];

    float4 sc4 = make_float4(1.f, 1.f, 1.f, 1.f);
    float4 sh4 = make_float4(0.f, 0.f, 0.f, 0.f);
    if (stats_in) {
        const float invN = 1.0f / (float)N_NODES;
        int f = lane * 4;
        float* scp = reinterpret_cast<float*>(&sc4);
        float* shp = reinterpret_cast<float*>(&sh4);
        #pragma unroll
        for (int i = 0; i < 4; i++) {
            float mu = stats_in[f + i] * invN;
            float var = fmaf(stats_in[DD + f + i], invN, -mu * mu);
            float sc = gm[f + i] * rsqrtf(var + BN_EPS);
            scp[i] = sc;
            shp[i] = bt[f + i] - mu * sc;
        }
    }

    for (int node = gwarp; node < N_NODES; node += nwarps) {
        int beg = g_off[node], end = g_off[node + 1];
        float4 xv = in[node * DV + lane];
        float4 acc = make_float4(0.f, 0.f, 0.f, 0.f);
        int e = beg;
        for (; e + 4 <= end; e += 4) {
            int j0 = g_csr[e], j1 = g_csr[e+1], j2 = g_csr[e+2], j3 = g_csr[e+3];
            float4 v0 = in[j0 * DV + lane];
            float4 v1 = in[j1 * DV + lane];
            float4 v2 = in[j2 * DV + lane];
            float4 v3 = in[j3 * DV + lane];
            acc.x += (v0.x + v1.x) + (v2.x + v3.x);
            acc.y += (v0.y + v1.y) + (v2.y + v3.y);
            acc.z += (v0.z + v1.z) + (v2.z + v3.z);
            acc.w += (v0.w + v1.w) + (v2.w + v3.w);
        }
        for (; e < end; e++) {
            float4 v0 = in[g_csr[e] * DV + lane];
            acc.x += v0.x; acc.y += v0.y; acc.z += v0.z; acc.w += v0.w;
        }
        float f = eps1 + (float)(end - beg);
        float h0 = fmaf(sc4.x, fmaf(eps1, xv.x, acc.x), f * sh4.x);
        float h1 = fmaf(sc4.y, fmaf(eps1, xv.y, acc.y), f * sh4.y);
        float h2 = fmaf(sc4.z, fmaf(eps1, xv.z, acc.z), f * sh4.z);
        float h3 = fmaf(sc4.w, fmaf(eps1, xv.w, acc.w), f * sh4.w);
        g_hhi[node * 32 + lane] = make_uint2(pack_bf16x2(h0, h1), pack_bf16x2(h2, h3));
        g_hlo[node * 32 + lane] = make_uint2(
            pack_bf16x2(h0 - bf_round(h0), h1 - bf_round(h1)),
            pack_bf16x2(h2 - bf_round(h2), h3 - bf_round(h3)));
    }
}

// ---------------- stats: per-feature sum/sumsq (high occupancy, reg accumulate) ----
__global__ void __launch_bounds__(256) k_stats(const float4* __restrict__ in,
                                               float* __restrict__ stats_out) {
    const int lane = threadIdx.x & 31;
    const int gwarp = (blockIdx.x * blockDim.x + threadIdx.x) >> 5;
    const int nwarps = (gridDim.x * blockDim.x) >> 5;
    float4 s = make_float4(0.f, 0.f, 0.f, 0.f);
    float4 q = make_float4(0.f, 0.f, 0.f, 0.f);
    for (int n = gwarp; n < N_NODES; n += nwarps) {
        float4 v = in[n * DV + lane];
        s.x += v.x; s.y += v.y; s.z += v.z; s.w += v.w;
        q.x += v.x*v.x; q.y += v.y*v.y; q.z += v.z*v.z; q.w += v.w*v.w;
    }
    int f = lane * 4;
    atomicAdd(&stats_out[f+0], s.x); atomicAdd(&stats_out[f+1], s.y);
    atomicAdd(&stats_out[f+2], s.z); atomicAdd(&stats_out[f+3], s.w);
    atomicAdd(&stats_out[DD+f+0], q.x); atomicAdd(&stats_out[DD+f+1], q.y);
    atomicAdd(&stats_out[DD+f+2], q.z); atomicAdd(&stats_out[DD+f+3], q.w);
}

// ---------------- GEMM: 2x bf16x3 mma.sync + epilogues (no stats) ----------------
extern __shared__ char kmsmem[];
__global__ void __launch_bounds__(256, 1) k_gemm(
    float4* __restrict__ out,
    const float* __restrict__ W1, const float* __restrict__ b1,
    const float* __restrict__ W2, const float* __restrict__ b2)
{
    const uint32_t sb = smem_u32(kmsmem);
    float* smemf = reinterpret_cast<float*>(kmsmem);
    const int t = threadIdx.x;
    const int lane = t & 31, wid = t >> 5;

    for (int i4 = t; i4 < DD * 32; i4 += 256) {
        int d = i4 >> 5, m = i4 & 31;
        float4 w1 = reinterpret_cast<const float4*>(W1)[i4];
        float4 w2 = reinterpret_cast<const float4*>(W2)[i4];
        uint32_t byte = (uint32_t)d * 256 + ((((uint32_t)(m >> 1)) ^ (d & 7)) << 4) + ((m & 1) << 3);
        *reinterpret_cast<uint2*>(kmsmem + OFF_W1 + byte) =
            make_uint2(pack_bf16x2(w1.x, w1.y), pack_bf16x2(w1.z, w1.w));
        *reinterpret_cast<uint2*>(kmsmem + OFF_W1 + WLO_OFF + byte) =
            make_uint2(pack_bf16x2(w1.x - bf_round(w1.x), w1.y - bf_round(w1.y)),
                       pack_bf16x2(w1.z - bf_round(w1.z), w1.w - bf_round(w1.w)));
        *reinterpret_cast<uint2*>(kmsmem + OFF_W2 + byte) =
            make_uint2(pack_bf16x2(w2.x, w2.y), pack_bf16x2(w2.z, w2.w));
        *reinterpret_cast<uint2*>(kmsmem + OFF_W2 + WLO_OFF + byte) =
            make_uint2(pack_bf16x2(w2.x - bf_round(w2.x), w2.y - bf_round(w2.y)),
                       pack_bf16x2(w2.z - bf_round(w2.z), w2.w - bf_round(w2.w)));
    }
    if (t < DD) { smemf[OFF_B1/4 + t] = b1[t]; smemf[OFF_B2/4 + t] = b2[t]; }
    __syncthreads();

    const int sel  = lane >> 3;
    const int rowA = (lane & 7) + (sel & 1) * 8;
    const int selk = sel >> 1;
    const int kofs = rowA;
    const int nsel = sel >> 1;
    const int l7   = lane & 7;
    const uint32_t aBase = sb + OFF_A + wid * 8192 + (uint32_t)rowA * 256;
    const uint32_t aWarp = sb + OFF_A + wid * 8192;
    const int q  = lane & 3;
    const int g8 = lane >> 2;

    for (int tile = blockIdx.x; tile < NTILES; tile += GRID_GEMM) {
        const int base_node = tile * TILE_M + wid * 16;

        // phase 1: copy pre-split H rows into swizzled A buffer
        #pragma unroll
        for (int r = 0; r < 16; r++) {
            int node = base_node + r;
            uint2 hi = make_uint2(0u, 0u), lo = make_uint2(0u, 0u);
            if (node < N_NODES) { hi = g_hhi[node * 32 + lane]; lo = g_hlo[node * 32 + lane]; }
            uint32_t off = (uint32_t)r * 256 + ((((uint32_t)(lane >> 1)) ^ (r & 7)) << 4) + ((lane & 1) << 3);
            *reinterpret_cast<uint2*>(kmsmem + (aWarp - sb) + off) = hi;
            *reinterpret_cast<uint2*>(kmsmem + (aWarp - sb) + 4096 + off) = lo;
        }
        __syncwarp();

        // GEMM1
        float acc[16][4];
        #pragma unroll
        for (int j = 0; j < 16; j++) { acc[j][0]=0.f; acc[j][1]=0.f; acc[j][2]=0.f; acc[j][3]=0.f; }
        gemm_chain(acc, aBase, sb + OFF_W1, selk, nsel, kofs, l7);
        __syncwarp();

        // epilogue 1: t = relu(d1 + b1) -> A buffer hi/lo
        #pragma unroll
        for (int j = 0; j < 16; j++) {
            int n0 = 8 * j + 2 * q;
            float be0 = smemf[OFF_B1/4 + n0], be1 = smemf[OFF_B1/4 + n0 + 1];
            float t0 = fmaxf(acc[j][0] + be0, 0.f);
            float t1 = fmaxf(acc[j][1] + be1, 0.f);
            float t2 = fmaxf(acc[j][2] + be0, 0.f);
            float t3 = fmaxf(acc[j][3] + be1, 0.f);
            uint32_t o0 = (uint32_t)g8 * 256 + (((uint32_t)j ^ (uint32_t)g8) << 4) + 4 * q;
            uint32_t o1 = o0 + 2048;
            char* ab = kmsmem + (aWarp - sb);
            *reinterpret_cast<uint32_t*>(ab + o0) = pack_bf16x2(t0, t1);
            *reinterpret_cast<uint32_t*>(ab + o1) = pack_bf16x2(t2, t3);
            *reinterpret_cast<uint32_t*>(ab + 4096 + o0) =
                pack_bf16x2(t0 - bf_round(t0), t1 - bf_round(t1));
            *reinterpret_cast<uint32_t*>(ab + 4096 + o1) =
                pack_bf16x2(t2 - bf_round(t2), t3 - bf_round(t3));
        }
        __syncwarp();

        // GEMM2
        #pragma unroll
        for (int j = 0; j < 16; j++) { acc[j][0]=0.f; acc[j][1]=0.f; acc[j][2]=0.f; acc[j][3]=0.f; }
        gemm_chain(acc, aBase, sb + OFF_W2, selk, nsel, kofs, l7);

        // epilogue 2: y = relu(d2 + b2); store
        {
            int node0 = base_node + g8;
            int node1 = node0 + 8;
            bool v0 = node0 < N_NODES, v1 = node1 < N_NODES;
            float2* outv2 = reinterpret_cast<float2*>(out);
            #pragma unroll
            for (int j = 0; j < 16; j++) {
                int n0 = 8 * j + 2 * q;
                float be0 = smemf[OFF_B2/4 + n0], be1 = smemf[OFF_B2/4 + n0 + 1];
                if (v0) outv2[node0 * 64 + 4 * j + q] =
                    make_float2(fmaxf(acc[j][0] + be0, 0.f), fmaxf(acc[j][1] + be1, 0.f));
                if (v1) outv2[node1 * 64 + 4 * j + q] =
                    make_float2(fmaxf(acc[j][2] + be0, 0.f), fmaxf(acc[j][3] + be1, 0.f));
            }
        }
        __syncwarp();
    }
}

// ---------------- pool (+ layer-3 stats) ----------------
__global__ void __launch_bounds__(256) k_pool(const int* __restrict__ batch,
                                              const float4* __restrict__ in,
                                              float* __restrict__ stats_out) {
    const int lane = threadIdx.x & 31;
    const int gwarp = (blockIdx.x * blockDim.x + threadIdx.x) >> 5;
    const int nwarps = (gridDim.x * blockDim.x) >> 5;
    float4 s = make_float4(0.f, 0.f, 0.f, 0.f);
    float4 q = make_float4(0.f, 0.f, 0.f, 0.f);
    for (int n = gwarp; n < N_NODES; n += nwarps) {
        unsigned g = (unsigned)batch[n];
        float4 v = in[n * DV + lane];
        s.x += v.x; s.y += v.y; s.z += v.z; s.w += v.w;
        q.x += v.x*v.x; q.y += v.y*v.y; q.z += v.z*v.z; q.w += v.w*v.w;
        if (g < N_GRAPHS) {
            atomicAdd(&g_pool[g * DV + lane], v);
            if (lane == 0) atomicAdd(&g_cnt[g], 1.0f);
        }
    }
    int f = lane * 4;
    atomicAdd(&stats_out[f+0], s.x); atomicAdd(&stats_out[f+1], s.y);
    atomicAdd(&stats_out[f+2], s.z); atomicAdd(&stats_out[f+3], s.w);
    atomicAdd(&stats_out[DD+f+0], q.x); atomicAdd(&stats_out[DD+f+1], q.y);
    atomicAdd(&stats_out[DD+f+2], q.z); atomicAdd(&stats_out[DD+f+3], q.w);
}

__global__ void k_final(const float* __restrict__ We, const float* __restrict__ be,
                        const float* __restrict__ gm, const float* __restrict__ bt,
                        float* __restrict__ out) {
    __shared__ float sp[DD];
    int b = blockIdx.x;
    int o = threadIdx.x;
    const float invN = 1.0f / (float)N_NODES;
    const float* st = g_stats + (NLAYERS - 1) * 2 * DD;
    float mu = st[o] * invN;
    float var = fmaf(st[DD + o], invN, -mu * mu);
    float sc = gm[o] * rsqrtf(var + BN_EPS);
    float sh = bt[o] - mu * sc;
    float c = fmaxf(g_cnt[b], 1.0f);
    float sum = reinterpret_cast<const float*>(g_pool)[b * DD + o];
    sp[o] = fmaf(sc, sum / c, sh);
    __syncthreads();
    float accv = be[o];
    #pragma unroll 4
    for (int d = 0; d < DD; d++) accv = fmaf(sp[d], We[d * DD + o], accv);
    out[b * DD + o] = accv;
}

extern "C" void kernel_launch(void* const* d_in, const int* in_sizes, int n_in,
                              void* d_out, int out_size) {
    const float* x     = (const float*)d_in[0];
    const int*   ei    = (const int*)d_in[1];
    const int*   batch = (const int*)d_in[2];
    const float* W1    = (const float*)d_in[3];
    const float* b1    = (const float*)d_in[4];
    const float* W2    = (const float*)d_in[5];
    const float* b2    = (const float*)d_in[6];
    const float* eps   = (const float*)d_in[7];
    const float* gamma = (const float*)d_in[8];
    const float* beta  = (const float*)d_in[9];
    const float* We    = (const float*)d_in[10];
    const float* be    = (const float*)d_in[11];
    float* out = (float*)d_out;

    void *p_xa, *p_xb, *p_deg, *p_cur, *p_stats, *p_pool, *p_cnt;
    cudaGetSymbolAddress(&p_xa, g_xa);
    cudaGetSymbolAddress(&p_xb, g_xb);
    cudaGetSymbolAddress(&p_deg, g_deg);
    cudaGetSymbolAddress(&p_cur, g_cur);
    cudaGetSymbolAddress(&p_stats, g_stats);
    cudaGetSymbolAddress(&p_pool, g_pool);
    cudaGetSymbolAddress(&p_cnt, g_cnt);
    float* stats = (float*)p_stats;

    cudaFuncSetAttribute(k_gemm, cudaFuncAttributeMaxDynamicSharedMemorySize, SMEM_KM);

    cudaMemcpyAsync(p_xa, x, (size_t)N_NODES * DD * sizeof(float),
                    cudaMemcpyDeviceToDevice, 0);

    cudaMemsetAsync(p_deg, 0, N_NODES * sizeof(int), 0);
    cudaMemsetAsync(p_cur, 0, N_NODES * sizeof(int), 0);
    cudaMemsetAsync(p_stats, 0, NLAYERS * 2 * DD * sizeof(float), 0);
    const int eb = (N_EDGES + 255) / 256;
    k_deg<<<eb, 256>>>(ei);
    k_scan<<<1, 1024>>>();
    k_fill<<<eb, 256>>>(ei);

    float4* bufs[4] = { (float4*)p_xa, (float4*)p_xb, (float4*)p_xa, (float4*)p_xb };
    for (int l = 0; l < NLAYERS; l++) {
        const float* st_in = (l == 0) ? nullptr : stats + (l - 1) * 2 * DD;
        const float* gm = (l == 0) ? gamma : gamma + (l - 1) * DD;
        const float* bt = (l == 0) ? beta  : beta  + (l - 1) * DD;
        k_gather<<<1184, 256>>>(bufs[l], st_in, gm, bt, eps + l);
        k_gemm<<<GRID_GEMM, 256, SMEM_KM>>>(bufs[l+1],
                                            W1 + l*DD*DD, b1 + l*DD,
                                            W2 + l*DD*DD, b2 + l*DD);
        if (l < NLAYERS - 1)
            k_stats<<<592, 256>>>(bufs[l+1], stats + l * 2 * DD);
    }

    cudaMemsetAsync(p_pool, 0, (size_t)N_GRAPHS * DD * sizeof(float), 0);
    cudaMemsetAsync(p_cnt, 0, N_GRAPHS * sizeof(float), 0);
    k_pool<<<592, 256>>>(batch, bufs[NLAYERS], stats + (NLAYERS - 1) * 2 * DD);
    k_final<<<N_GRAPHS, DD>>>(We, be, gamma + (NLAYERS-1)*DD, beta + (NLAYERS-1)*DD, out);
}

// round 10
// speedup vs baseline: 1.7003x; 1.7003x over previous
#include <cuda_runtime.h>
#include <cuda_bf16.h>
#include <cstdint>

#define N_NODES 50000
#define N_EDGES 800000
#define N_GRAPHS 256
#define DD 128
#define DV 32
#define NLAYERS 3
#define TILE_M 128
#define NTILES ((N_NODES + TILE_M - 1) / TILE_M)
#define BN_EPS 1e-5f
#define GRID_GEMM 148

// ---- k_gemm smem layout (bytes) ----
#define OFF_W1   0
#define OFF_W2   65536
#define WLO_OFF  32768
#define OFF_A    131072          // 8 warps x 8KB (hi at +0, lo at +4096)
#define OFF_B1   196608
#define OFF_B2   197120
#define OFF_STAT 197632
#define SMEM_KM  198656

__device__ __forceinline__ uint32_t smem_u32(const void* p) {
    uint32_t a;
    asm("{ .reg .u64 t; cvta.to.shared.u64 t, %1; cvt.u32.u64 %0, t; }" : "=r"(a) : "l"(p));
    return a;
}
__device__ __forceinline__ uint32_t pack_bf16x2(float a, float b) {
    uint32_t r;
    asm("cvt.rn.bf16x2.f32 %0, %1, %2;" : "=r"(r) : "f"(b), "f"(a));
    return r;
}
__device__ __forceinline__ float bf_round(float v) {
    return __bfloat162float(__float2bfloat16(v));
}
__device__ __forceinline__ void ldsm_x4(uint32_t* r, uint32_t addr) {
    asm volatile("ldmatrix.sync.aligned.m8n8.x4.shared.b16 {%0,%1,%2,%3}, [%4];"
                 : "=r"(r[0]), "=r"(r[1]), "=r"(r[2]), "=r"(r[3]) : "r"(addr));
}
__device__ __forceinline__ void ldsm_x4_t(uint32_t* r, uint32_t addr) {
    asm volatile("ldmatrix.sync.aligned.m8n8.x4.trans.shared.b16 {%0,%1,%2,%3}, [%4];"
                 : "=r"(r[0]), "=r"(r[1]), "=r"(r[2]), "=r"(r[3]) : "r"(addr));
}
__device__ __forceinline__ void mma16816(float* c, const uint32_t* a, uint32_t b0, uint32_t b1) {
    asm volatile(
        "mma.sync.aligned.m16n8k16.row.col.f32.bf16.bf16.f32 "
        "{%0,%1,%2,%3}, {%4,%5,%6,%7}, {%8,%9}, {%0,%1,%2,%3};"
        : "+f"(c[0]), "+f"(c[1]), "+f"(c[2]), "+f"(c[3])
        : "r"(a[0]), "r"(a[1]), "r"(a[2]), "r"(a[3]), "r"(b0), "r"(b1));
}

__device__ __forceinline__ void gemm_chain(float (*acc)[4], uint32_t aBase, uint32_t bBase,
                                           int selk, int nsel, int kofs, int l7) {
    #pragma unroll 1
    for (int ks = 0; ks < 8; ks++) {
        uint32_t ah[4], al[4];
        uint32_t aaddr = aBase + (uint32_t)(((2 * ks + selk) ^ l7) << 4);
        ldsm_x4(ah, aaddr);
        ldsm_x4(al, aaddr + 4096);
        uint32_t bRow = bBase + (uint32_t)(16 * ks + kofs) * 256;
        #pragma unroll
        for (int jp = 0; jp < 8; jp++) {
            uint32_t bh[4], bl[4];
            uint32_t baddr = bRow + (uint32_t)(((2 * jp + nsel) ^ l7) << 4);
            ldsm_x4_t(bh, baddr);
            ldsm_x4_t(bl, baddr + WLO_OFF);
            mma16816(acc[2*jp],   ah, bh[0], bh[1]);
            mma16816(acc[2*jp+1], ah, bh[2], bh[3]);
            mma16816(acc[2*jp],   al, bh[0], bh[1]);
            mma16816(acc[2*jp+1], al, bh[2], bh[3]);
            mma16816(acc[2*jp],   ah, bl[0], bl[1]);
            mma16816(acc[2*jp+1], ah, bl[2], bl[3]);
        }
    }
}

// ---------------- scratch ----------------
__device__ float4 g_xa[N_NODES * DV];
__device__ float4 g_xb[N_NODES * DV];
__device__ uint2  g_hhi[N_NODES * 32];
__device__ uint2  g_hlo[N_NODES * 32];
__device__ int    g_deg[N_NODES];
__device__ int    g_off[N_NODES + 1];
__device__ int    g_cur[N_NODES];
__device__ int    g_csr[N_EDGES];
__device__ float  g_stats[NLAYERS * 2 * DD];
__device__ float4 g_pool[N_GRAPHS * DV];
__device__ float  g_cnt[N_GRAPHS];

// ---------------- CSR build ----------------
__global__ void k_deg(const int* __restrict__ ei) {
    int e = blockIdx.x * blockDim.x + threadIdx.x;
    if (e >= N_EDGES) return;
    unsigned d = (unsigned)ei[N_EDGES + e];
    if (d < N_NODES) atomicAdd(&g_deg[d], 1);
}
__global__ void k_scan() {
    __shared__ int sbuf[1024];
    __shared__ int carry;
    if (threadIdx.x == 0) carry = 0;
    __syncthreads();
    for (int base = 0; base < N_NODES; base += 1024) {
        int i = base + threadIdx.x;
        int v = (i < N_NODES) ? g_deg[i] : 0;
        sbuf[threadIdx.x] = v;
        __syncthreads();
        for (int ofs = 1; ofs < 1024; ofs <<= 1) {
            int tv = (threadIdx.x >= ofs) ? sbuf[threadIdx.x - ofs] : 0;
            __syncthreads();
            sbuf[threadIdx.x] += tv;
            __syncthreads();
        }
        if (i < N_NODES) g_off[i + 1] = carry + sbuf[threadIdx.x];
        __syncthreads();
        if (threadIdx.x == 0) carry += sbuf[1023];
        __syncthreads();
    }
    if (threadIdx.x == 0) g_off[0] = 0;
}
__global__ void k_fill(const int* __restrict__ ei) {
    int e = blockIdx.x * blockDim.x + threadIdx.x;
    if (e >= N_EDGES) return;
    unsigned s = (unsigned)ei[e];
    unsigned d = (unsigned)ei[N_EDGES + e];
    if (s >= N_NODES || d >= N_NODES) return;
    int pos = atomicAdd(&g_cur[d], 1);
    g_csr[g_off[d] + pos] = (int)s;
}

// ---------------- gather: CSR walk + GIN combine + BN fold -> H hi/lo ----------------
__global__ void __launch_bounds__(256) k_gather(
    const float4* __restrict__ in,
    const float* __restrict__ stats_in,
    const float* __restrict__ gm, const float* __restrict__ bt,
    const float* __restrict__ epsp)
{
    const int lane = threadIdx.x & 31;
    const int gwarp = (blockIdx.x * blockDim.x + threadIdx.x) >> 5;
    const int nwarps = (gridDim.x * blockDim.x) >> 5;
    const float eps1 = 1.0f + epsp[0];

    float4 sc4 = make_float4(1.f, 1.f, 1.f, 1.f);
    float4 sh4 = make_float4(0.f, 0.f, 0.f, 0.f);
    if (stats_in) {
        const float invN = 1.0f / (float)N_NODES;
        int f = lane * 4;
        float* scp = reinterpret_cast<float*>(&sc4);
        float* shp = reinterpret_cast<float*>(&sh4);
        #pragma unroll
        for (int i = 0; i < 4; i++) {
            float mu = stats_in[f + i] * invN;
            float var = fmaf(stats_in[DD + f + i], invN, -mu * mu);
            float sc = gm[f + i] * rsqrtf(var + BN_EPS);
            scp[i] = sc;
            shp[i] = bt[f + i] - mu * sc;
        }
    }

    for (int node = gwarp; node < N_NODES; node += nwarps) {
        int beg = g_off[node], end = g_off[node + 1];
        float4 xv = in[node * DV + lane];
        float4 acc = make_float4(0.f, 0.f, 0.f, 0.f);
        int e = beg;
        for (; e + 4 <= end; e += 4) {
            int j0 = g_csr[e], j1 = g_csr[e+1], j2 = g_csr[e+2], j3 = g_csr[e+3];
            float4 v0 = in[j0 * DV + lane];
            float4 v1 = in[j1 * DV + lane];
            float4 v2 = in[j2 * DV + lane];
            float4 v3 = in[j3 * DV + lane];
            acc.x += (v0.x + v1.x) + (v2.x + v3.x);
            acc.y += (v0.y + v1.y) + (v2.y + v3.y);
            acc.z += (v0.z + v1.z) + (v2.z + v3.z);
            acc.w += (v0.w + v1.w) + (v2.w + v3.w);
        }
        for (; e < end; e++) {
            float4 v0 = in[g_csr[e] * DV + lane];
            acc.x += v0.x; acc.y += v0.y; acc.z += v0.z; acc.w += v0.w;
        }
        float f = eps1 + (float)(end - beg);
        float h0 = fmaf(sc4.x, fmaf(eps1, xv.x, acc.x), f * sh4.x);
        float h1 = fmaf(sc4.y, fmaf(eps1, xv.y, acc.y), f * sh4.y);
        float h2 = fmaf(sc4.z, fmaf(eps1, xv.z, acc.z), f * sh4.z);
        float h3 = fmaf(sc4.w, fmaf(eps1, xv.w, acc.w), f * sh4.w);
        g_hhi[node * 32 + lane] = make_uint2(pack_bf16x2(h0, h1), pack_bf16x2(h2, h3));
        g_hlo[node * 32 + lane] = make_uint2(
            pack_bf16x2(h0 - bf_round(h0), h1 - bf_round(h1)),
            pack_bf16x2(h2 - bf_round(h2), h3 - bf_round(h3)));
    }
}

// ---------------- GEMM: 2x bf16x3 mma.sync + epilogues + BN stats ----------------
extern __shared__ char kmsmem[];
__global__ void __launch_bounds__(256, 1) k_gemm(
    float4* __restrict__ out,
    const float* __restrict__ W1, const float* __restrict__ b1,
    const float* __restrict__ W2, const float* __restrict__ b2,
    float* __restrict__ stats_out)
{
    const uint32_t sb = smem_u32(kmsmem);
    float* smemf = reinterpret_cast<float*>(kmsmem);
    const int t = threadIdx.x;
    const int lane = t & 31, wid = t >> 5;

    for (int i4 = t; i4 < DD * 32; i4 += 256) {
        int d = i4 >> 5, m = i4 & 31;
        float4 w1 = reinterpret_cast<const float4*>(W1)[i4];
        float4 w2 = reinterpret_cast<const float4*>(W2)[i4];
        uint32_t byte = (uint32_t)d * 256 + ((((uint32_t)(m >> 1)) ^ (d & 7)) << 4) + ((m & 1) << 3);
        *reinterpret_cast<uint2*>(kmsmem + OFF_W1 + byte) =
            make_uint2(pack_bf16x2(w1.x, w1.y), pack_bf16x2(w1.z, w1.w));
        *reinterpret_cast<uint2*>(kmsmem + OFF_W1 + WLO_OFF + byte) =
            make_uint2(pack_bf16x2(w1.x - bf_round(w1.x), w1.y - bf_round(w1.y)),
                       pack_bf16x2(w1.z - bf_round(w1.z), w1.w - bf_round(w1.w)));
        *reinterpret_cast<uint2*>(kmsmem + OFF_W2 + byte) =
            make_uint2(pack_bf16x2(w2.x, w2.y), pack_bf16x2(w2.z, w2.w));
        *reinterpret_cast<uint2*>(kmsmem + OFF_W2 + WLO_OFF + byte) =
            make_uint2(pack_bf16x2(w2.x - bf_round(w2.x), w2.y - bf_round(w2.y)),
                       pack_bf16x2(w2.z - bf_round(w2.z), w2.w - bf_round(w2.w)));
    }
    if (t < DD) { smemf[OFF_B1/4 + t] = b1[t]; smemf[OFF_B2/4 + t] = b2[t]; }
    smemf[OFF_STAT/4 + t] = 0.0f;
    __syncthreads();

    const int sel  = lane >> 3;
    const int rowA = (lane & 7) + (sel & 1) * 8;
    const int selk = sel >> 1;
    const int kofs = rowA;
    const int nsel = sel >> 1;
    const int l7   = lane & 7;
    const uint32_t aBase = sb + OFF_A + wid * 8192 + (uint32_t)rowA * 256;
    const uint32_t aWarp = sb + OFF_A + wid * 8192;
    const int q  = lane & 3;
    const int g8 = lane >> 2;

    for (int tile = blockIdx.x; tile < NTILES; tile += GRID_GEMM) {
        const int base_node = tile * TILE_M + wid * 16;

        // phase 1: copy pre-split H rows into swizzled A buffer
        #pragma unroll
        for (int r = 0; r < 16; r++) {
            int node = base_node + r;
            uint2 hi = make_uint2(0u, 0u), lo = make_uint2(0u, 0u);
            if (node < N_NODES) { hi = g_hhi[node * 32 + lane]; lo = g_hlo[node * 32 + lane]; }
            uint32_t off = (uint32_t)r * 256 + ((((uint32_t)(lane >> 1)) ^ (r & 7)) << 4) + ((lane & 1) << 3);
            *reinterpret_cast<uint2*>(kmsmem + (aWarp - sb) + off) = hi;
            *reinterpret_cast<uint2*>(kmsmem + (aWarp - sb) + 4096 + off) = lo;
        }
        __syncwarp();

        // GEMM1
        float acc[16][4];
        #pragma unroll
        for (int j = 0; j < 16; j++) { acc[j][0]=0.f; acc[j][1]=0.f; acc[j][2]=0.f; acc[j][3]=0.f; }
        gemm_chain(acc, aBase, sb + OFF_W1, selk, nsel, kofs, l7);
        __syncwarp();

        // epilogue 1: t = relu(d1 + b1) -> A buffer hi/lo
        #pragma unroll
        for (int j = 0; j < 16; j++) {
            int n0 = 8 * j + 2 * q;
            float be0 = smemf[OFF_B1/4 + n0], be1 = smemf[OFF_B1/4 + n0 + 1];
            float t0 = fmaxf(acc[j][0] + be0, 0.f);
            float t1 = fmaxf(acc[j][1] + be1, 0.f);
            float t2 = fmaxf(acc[j][2] + be0, 0.f);
            float t3 = fmaxf(acc[j][3] + be1, 0.f);
            uint32_t o0 = (uint32_t)g8 * 256 + (((uint32_t)j ^ (uint32_t)g8) << 4) + 4 * q;
            uint32_t o1 = o0 + 2048;
            char* ab = kmsmem + (aWarp - sb);
            *reinterpret_cast<uint32_t*>(ab + o0) = pack_bf16x2(t0, t1);
            *reinterpret_cast<uint32_t*>(ab + o1) = pack_bf16x2(t2, t3);
            *reinterpret_cast<uint32_t*>(ab + 4096 + o0) =
                pack_bf16x2(t0 - bf_round(t0), t1 - bf_round(t1));
            *reinterpret_cast<uint32_t*>(ab + 4096 + o1) =
                pack_bf16x2(t2 - bf_round(t2), t3 - bf_round(t3));
        }
        __syncwarp();

        // GEMM2
        #pragma unroll
        for (int j = 0; j < 16; j++) { acc[j][0]=0.f; acc[j][1]=0.f; acc[j][2]=0.f; acc[j][3]=0.f; }
        gemm_chain(acc, aBase, sb + OFF_W2, selk, nsel, kofs, l7);

        // epilogue 2: y = relu(d2 + b2); store; BN stats (smem-staged)
        {
            int node0 = base_node + g8;
            int node1 = node0 + 8;
            bool v0 = node0 < N_NODES, v1 = node1 < N_NODES;
            float2* outv2 = reinterpret_cast<float2*>(out);
            #pragma unroll
            for (int j = 0; j < 16; j++) {
                int n0 = 8 * j + 2 * q;
                float be0 = smemf[OFF_B2/4 + n0], be1 = smemf[OFF_B2/4 + n0 + 1];
                float y0 = fmaxf(acc[j][0] + be0, 0.f);
                float y1 = fmaxf(acc[j][1] + be1, 0.f);
                float y2 = fmaxf(acc[j][2] + be0, 0.f);
                float y3 = fmaxf(acc[j][3] + be1, 0.f);
                if (v0) outv2[node0 * 64 + 4 * j + q] = make_float2(y0, y1);
                if (v1) outv2[node1 * 64 + 4 * j + q] = make_float2(y2, y3);
                float se = (v0 ? y0 : 0.f) + (v1 ? y2 : 0.f);
                float so = (v0 ? y1 : 0.f) + (v1 ? y3 : 0.f);
                float qe = (v0 ? y0*y0 : 0.f) + (v1 ? y2*y2 : 0.f);
                float qo = (v0 ? y1*y1 : 0.f) + (v1 ? y3*y3 : 0.f);
                #pragma unroll
                for (int off = 4; off < 32; off <<= 1) {
                    se += __shfl_xor_sync(0xFFFFFFFFu, se, off);
                    so += __shfl_xor_sync(0xFFFFFFFFu, so, off);
                    qe += __shfl_xor_sync(0xFFFFFFFFu, qe, off);
                    qo += __shfl_xor_sync(0xFFFFFFFFu, qo, off);
                }
                if (g8 == 0) {
                    atomicAdd(&smemf[OFF_STAT/4 + n0],           se);
                    atomicAdd(&smemf[OFF_STAT/4 + n0 + 1],       so);
                    atomicAdd(&smemf[OFF_STAT/4 + 128 + n0],     qe);
                    atomicAdd(&smemf[OFF_STAT/4 + 128 + n0 + 1], qo);
                }
            }
        }
        __syncwarp();
    }

    __syncthreads();
    atomicAdd(&stats_out[t], smemf[OFF_STAT/4 + t]);
}

// ---------------- pool + head ----------------
__global__ void k_pool(const int* __restrict__ batch, const float4* __restrict__ in) {
    int idx = blockIdx.x * blockDim.x + threadIdx.x;
    int n = idx >> 5;
    int k = idx & 31;
    if (n >= N_NODES) return;
    unsigned g = (unsigned)batch[n];
    if (g >= N_GRAPHS) return;
    float4 v = in[n * DV + k];
    atomicAdd(&g_pool[g * DV + k], v);
    if (k == 0) atomicAdd(&g_cnt[g], 1.0f);
}

__global__ void k_final(const float* __restrict__ We, const float* __restrict__ be,
                        const float* __restrict__ gm, const float* __restrict__ bt,
                        float* __restrict__ out) {
    __shared__ float sp[DD];
    int b = blockIdx.x;
    int o = threadIdx.x;
    const float invN = 1.0f / (float)N_NODES;
    const float* st = g_stats + (NLAYERS - 1) * 2 * DD;
    float mu = st[o] * invN;
    float var = fmaf(st[DD + o], invN, -mu * mu);
    float sc = gm[o] * rsqrtf(var + BN_EPS);
    float sh = bt[o] - mu * sc;
    float c = fmaxf(g_cnt[b], 1.0f);
    float sum = reinterpret_cast<const float*>(g_pool)[b * DD + o];
    sp[o] = fmaf(sc, sum / c, sh);
    __syncthreads();
    float accv = be[o];
    #pragma unroll 4
    for (int d = 0; d < DD; d++) accv = fmaf(sp[d], We[d * DD + o], accv);
    out[b * DD + o] = accv;
}

extern "C" void kernel_launch(void* const* d_in, const int* in_sizes, int n_in,
                              void* d_out, int out_size) {
    const float* x     = (const float*)d_in[0];
    const int*   ei    = (const int*)d_in[1];
    const int*   batch = (const int*)d_in[2];
    const float* W1    = (const float*)d_in[3];
    const float* b1    = (const float*)d_in[4];
    const float* W2    = (const float*)d_in[5];
    const float* b2    = (const float*)d_in[6];
    const float* eps   = (const float*)d_in[7];
    const float* gamma = (const float*)d_in[8];
    const float* beta  = (const float*)d_in[9];
    const float* We    = (const float*)d_in[10];
    const float* be    = (const float*)d_in[11];
    float* out = (float*)d_out;

    void *p_xa, *p_xb, *p_deg, *p_cur, *p_stats, *p_pool, *p_cnt;
    cudaGetSymbolAddress(&p_xa, g_xa);
    cudaGetSymbolAddress(&p_xb, g_xb);
    cudaGetSymbolAddress(&p_deg, g_deg);
    cudaGetSymbolAddress(&p_cur, g_cur);
    cudaGetSymbolAddress(&p_stats, g_stats);
    cudaGetSymbolAddress(&p_pool, g_pool);
    cudaGetSymbolAddress(&p_cnt, g_cnt);
    float* stats = (float*)p_stats;

    cudaFuncSetAttribute(k_gemm, cudaFuncAttributeMaxDynamicSharedMemorySize, SMEM_KM);

    cudaMemsetAsync(p_deg, 0, N_NODES * sizeof(int), 0);
    cudaMemsetAsync(p_cur, 0, N_NODES * sizeof(int), 0);
    cudaMemsetAsync(p_stats, 0, NLAYERS * 2 * DD * sizeof(float), 0);
    const int eb = (N_EDGES + 255) / 256;
    k_deg<<<eb, 256>>>(ei);
    k_scan<<<1, 1024>>>();
    k_fill<<<eb, 256>>>(ei);

    // layer 0 reads the harness input buffer directly (no memcpy)
    const float4* bufs_in[3]  = { (const float4*)x, (const float4*)p_xa, (const float4*)p_xb };
    float4*       bufs_out[3] = { (float4*)p_xa, (float4*)p_xb, (float4*)p_xa };
    for (int l = 0; l < NLAYERS; l++) {
        const float* st_in = (l == 0) ? nullptr : stats + (l - 1) * 2 * DD;
        const float* gm = (l == 0) ? gamma : gamma + (l - 1) * DD;
        const float* bt = (l == 0) ? beta  : beta  + (l - 1) * DD;
        k_gather<<<1184, 256>>>(bufs_in[l], st_in, gm, bt, eps + l);
        k_gemm<<<GRID_GEMM, 256, SMEM_KM>>>(bufs_out[l],
                                            W1 + l*DD*DD, b1 + l*DD,
                                            W2 + l*DD*DD, b2 + l*DD,
                                            stats + l * 2 * DD);
    }

    cudaMemsetAsync(p_pool, 0, (size_t)N_GRAPHS * DD * sizeof(float), 0);
    cudaMemsetAsync(p_cnt, 0, N_GRAPHS * sizeof(float), 0);
    const int pool_blocks = (N_NODES * 32 + 255) / 256;
    k_pool<<<pool_blocks, 256>>>(batch, bufs_out[NLAYERS - 1]);
    k_final<<<N_GRAPHS, DD>>>(We, be, gamma + (NLAYERS-1)*DD, beta + (NLAYERS-1)*DD, out);
}